// round 15
// baseline (speedup 1.0000x reference)
#include <cuda_runtime.h>
#include <cuda_bf16.h>
#include <cuda_fp16.h>
#include <math.h>
#include <stddef.h>
#include <stdint.h>

// ---------------- problem constants ----------------
#define SEQ      33600
#define DMODEL   256
#define NHEADS   8
#define NLEVELS  3
#define NPOINTS  4
#define LP       (NLEVELS * NPOINTS)        // 12
#define HD       (DMODEL / NHEADS)          // 32
#define NOFF     (NHEADS * LP * 2)          // 192
#define NATT     (NHEADS * LP)              // 96
#define N2       (NOFF + NATT)              // 288
#define KHL      512                         // weight hi|lo width
#define VROWS    (SEQ + 4)                   // padded rows per head
#define COPY_ELEMS ((size_t)NHEADS * VROWS * HD)
#define COPYSZB  ((int)(COPY_ELEMS * 2))
#define OUT_ELEMS  ((size_t)SEQ * DMODEL)
#define ATTN_ELEMS ((size_t)SEQ * NHEADS * LP)

#define GEMM_SMEM  (3 * 32768)               // 3 stages x (16KB A + 16KB B)

// ---------------- scratch (device globals) ----------------
__device__ __half g_val2[2 * COPY_ELEMS];     // value, head-major, copies A|B(shifted)
__device__ float  g_raw [SEQ * N2];
__device__ float  g_b2  [N2];
__device__ __half g_ench [SEQ * DMODEL];      // enc        fp16
__device__ __half g_hsh  [SEQ * DMODEL];      // hidden+pos fp16
__device__ __half g_samph[SEQ * DMODEL];      // sampled    fp16
__device__ __half g_wvh[DMODEL * KHL];        // weights fp16 hi|lo
__device__ __half g_w2h[N2 * KHL];
__device__ __half g_woh[DMODEL * KHL];

// ---------------- helpers ----------------
__device__ __forceinline__ uint32_t pack_h2(__half a, __half b) {
    __half2 t = __halves2half2(a, b);
    return *reinterpret_cast<uint32_t*>(&t);
}
__device__ __forceinline__ void split_f16(float x, __half& h, __half& l) {
    h = __float2half_rn(x);
    l = __float2half_rn(x - __half2float(h));
}
__device__ __forceinline__ void cvt8_hilo(float4 a, float4 b, uint4& H, uint4& L) {
    __half h[8], l[8];
    split_f16(a.x, h[0], l[0]); split_f16(a.y, h[1], l[1]);
    split_f16(a.z, h[2], l[2]); split_f16(a.w, h[3], l[3]);
    split_f16(b.x, h[4], l[4]); split_f16(b.y, h[5], l[5]);
    split_f16(b.z, h[6], l[6]); split_f16(b.w, h[7], l[7]);
    H = make_uint4(pack_h2(h[0],h[1]), pack_h2(h[2],h[3]), pack_h2(h[4],h[5]), pack_h2(h[6],h[7]));
    L = make_uint4(pack_h2(l[0],l[1]), pack_h2(l[2],l[3]), pack_h2(l[4],l[5]), pack_h2(l[6],l[7]));
}
__device__ __forceinline__ uint4 cvt8_f16(float4 a, float4 b) {
    __half2 p0 = __floats2half2_rn(a.x, a.y);
    __half2 p1 = __floats2half2_rn(a.z, a.w);
    __half2 p2 = __floats2half2_rn(b.x, b.y);
    __half2 p3 = __floats2half2_rn(b.z, b.w);
    return make_uint4(*(uint32_t*)&p0, *(uint32_t*)&p1, *(uint32_t*)&p2, *(uint32_t*)&p3);
}
__device__ __forceinline__ void cp_async16(uint32_t dst, const void* src, bool pred) {
    int sz = pred ? 16 : 0;
    asm volatile("cp.async.cg.shared.global [%0], [%1], 16, %2;"
                 :: "r"(dst), "l"(src), "r"(sz) : "memory");
}
// packed f32x2 helpers (sm_100+ base feature)
__device__ __forceinline__ unsigned long long pack_f32x2(float lo, float hi) {
    unsigned long long r;
    asm("mov.b64 %0, {%1, %2};" : "=l"(r) : "f"(lo), "f"(hi));
    return r;
}
__device__ __forceinline__ void unpack_f32x2(unsigned long long v, float& lo, float& hi) {
    asm("mov.b64 {%0, %1}, %2;" : "=f"(lo), "=f"(hi) : "l"(v));
}
__device__ __forceinline__ void fma_f32x2(unsigned long long& d,
                                          unsigned long long a, unsigned long long b) {
    asm("fma.rn.f32x2 %0, %1, %2, %0;" : "+l"(d) : "l"(a), "l"(b));
}
__device__ __forceinline__ unsigned long long add_f32x2(unsigned long long a, unsigned long long b) {
    unsigned long long r;
    asm("add.rn.f32x2 %0, %1, %2;" : "=l"(r) : "l"(a), "l"(b));
    return r;
}

// ---------------- merged prep + activation conversion ----------------
__global__ __launch_bounds__(256) void prep_conv_kernel(
    const float* __restrict__ Wv, const float* __restrict__ Ws, const float* __restrict__ bs,
    const float* __restrict__ Wa, const float* __restrict__ ba, const float* __restrict__ Wo,
    const float* __restrict__ enc, const float* __restrict__ hidden, const float* __restrict__ pos)
{
    if (blockIdx.x < 100) {
        int u = blockIdx.x * 256 + threadIdx.x;     // one unit = 8 floats
        const int TOTAL_ROWS = DMODEL + N2 + DMODEL;  // 800
        if (u < TOTAL_ROWS * 32) {
            int row = u >> 5, uc = u & 31;
            const float* src;
            __half* dst;
            if (row < DMODEL) { src = Wv + (size_t)row * DMODEL; dst = g_wvh + (size_t)row * KHL; }
            else if (row < DMODEL + N2) {
                int n = row - DMODEL;
                src = (n < NOFF) ? (Ws + (size_t)n * DMODEL) : (Wa + (size_t)(n - NOFF) * DMODEL);
                dst = g_w2h + (size_t)n * KHL;
            } else {
                int n = row - DMODEL - N2;
                src = Wo + (size_t)n * DMODEL; dst = g_woh + (size_t)n * KHL;
            }
            float4 a = *(const float4*)(src + uc * 8);
            float4 b = *(const float4*)(src + uc * 8 + 4);
            uint4 H, L; cvt8_hilo(a, b, H, L);
            *(uint4*)(dst + uc * 8)          = H;
            *(uint4*)(dst + DMODEL + uc * 8) = L;
        }
        if (u < N2) g_b2[u] = (u < NOFF) ? bs[u] : ba[u - NOFF];
    } else {
        int u = (blockIdx.x - 100) * 256 + threadIdx.x;
        const int PER = SEQ * 32;                 // units per tensor (8 floats each)
        if (u >= 2 * PER) return;
        bool second = (u >= PER);
        int v = second ? (u - PER) : u;
        int row = v >> 5, uc = v & 31;
        const float* src = (second ? hidden : enc) + (size_t)row * DMODEL + uc * 8;
        float4 a = *(const float4*)(src);
        float4 b = *(const float4*)(src + 4);
        if (second) {
            const float* p2 = pos + (size_t)row * DMODEL + uc * 8;
            float4 u0 = *(const float4*)p2, u1 = *(const float4*)(p2 + 4);
            a.x += u0.x; a.y += u0.y; a.z += u0.z; a.w += u0.w;
            b.x += u1.x; b.y += u1.y; b.z += u1.z; b.w += u1.w;
        }
        __half* dst = (second ? g_hsh : g_ench) + (size_t)row * DMODEL;
        *(uint4*)(dst + uc * 8) = cvt8_f16(a, b);
    }
}

// ---------------- GEMM: C[M,N] = A @ Bw^T + bias (fp16 A, fp16 hi/lo B, 2 passes) ----------------
struct GemmJob {
    const __half* A;
    const __half* Bw;
    const float* bias;
    void* C;
    int N;
    int out_half;   // 1: write __half head-major dual-copy (value), 0: write float
};

__global__ __launch_bounds__(256, 2) void gemm_kernel(GemmJob j0, GemmJob j1, int xsplit, int M)
{
    extern __shared__ char smem[];   // 3 stages x (16KB A + 16KB B)

    const bool first = ((int)blockIdx.x < xsplit);
    GemmJob j = first ? j0 : j1;
    const int nb = first ? blockIdx.x : (blockIdx.x - xsplit);
    const int blk_m = blockIdx.y * 128, blk_n = nb * 128;

    const int tid = threadIdx.x;
    const int wid = tid >> 5, lane = tid & 31;
    const int warp_m = wid & 3, warp_n = wid >> 2;
    const int t4 = lane >> 3, r8 = lane & 7;

    const uint32_t s_base = (uint32_t)__cvta_generic_to_shared(smem);

    int lrow[4], luc[4];
    uint32_t s_off[4];
    bool predA[4], predB[4];
    const __half* srcA[4];
    const __half* srcB[4];
    #pragma unroll
    for (int i = 0; i < 4; i++) {
        int u = tid + 256 * i;
        lrow[i] = u >> 3; luc[i] = u & 7;
        s_off[i] = (uint32_t)(lrow[i] * 128 + ((luc[i] ^ (lrow[i] & 7)) << 4));
        int gm = blk_m + lrow[i];
        predA[i] = gm < M;
        srcA[i] = j.A + (size_t)(predA[i] ? gm : 0) * DMODEL + luc[i] * 8;
        int gn = blk_n + lrow[i];
        predB[i] = gn < j.N;
        srcB[i] = j.Bw + (size_t)(predB[i] ? gn : 0) * KHL + luc[i] * 8;
    }

    float acc[2][8][4];
    #pragma unroll
    for (int a = 0; a < 2; a++)
        #pragma unroll
        for (int b = 0; b < 8; b++)
            #pragma unroll
            for (int c = 0; c < 4; c++) acc[a][b][c] = 0.f;

    auto issue = [&](int c, int buf) {
        int pass = c >> 2, kk = (c & 3) * 64;
        int bcol = pass * DMODEL + kk;
        uint32_t abase = s_base + buf * 32768;
        uint32_t bbase = abase + 16384;
        #pragma unroll
        for (int i = 0; i < 4; i++) {
            cp_async16(abase + s_off[i], srcA[i] + kk,   predA[i]);
            cp_async16(bbase + s_off[i], srcB[i] + bcol, predB[i]);
        }
        asm volatile("cp.async.commit_group;" ::: "memory");
    };

    issue(0, 0);
    issue(1, 1);

    for (int c = 0; c < 8; c++) {
        if (c + 2 < 8) {
            issue(c + 2, (c + 2) % 3);
            asm volatile("cp.async.wait_group 2;" ::: "memory");
        } else if (c == 6) {
            asm volatile("cp.async.wait_group 1;" ::: "memory");
        } else {
            asm volatile("cp.async.wait_group 0;" ::: "memory");
        }
        __syncthreads();

        const uint32_t abase = s_base + (c % 3) * 32768;
        const uint32_t bbase = abase + 16384;

        #pragma unroll
        for (int ks = 0; ks < 4; ks++) {
            uint32_t af[2][4];
            #pragma unroll
            for (int mi = 0; mi < 2; mi++) {
                int row = warp_m * 32 + mi * 16 + (t4 & 1) * 8 + r8;
                int kch = ks * 2 + (t4 >> 1);
                uint32_t addr = abase + (uint32_t)(row * 128 + ((kch ^ (row & 7)) << 4));
                asm volatile("ldmatrix.sync.aligned.m8n8.x4.shared.b16 {%0,%1,%2,%3}, [%4];"
                             : "=r"(af[mi][0]), "=r"(af[mi][1]), "=r"(af[mi][2]), "=r"(af[mi][3])
                             : "r"(addr));
            }
            uint32_t bf[4][4];
            #pragma unroll
            for (int jj = 0; jj < 4; jj++) {
                int nrow = warp_n * 64 + jj * 16 + (t4 >> 1) * 8 + r8;
                int kch = ks * 2 + (t4 & 1);
                uint32_t addr = bbase + (uint32_t)(nrow * 128 + ((kch ^ (nrow & 7)) << 4));
                asm volatile("ldmatrix.sync.aligned.m8n8.x4.shared.b16 {%0,%1,%2,%3}, [%4];"
                             : "=r"(bf[jj][0]), "=r"(bf[jj][1]), "=r"(bf[jj][2]), "=r"(bf[jj][3])
                             : "r"(addr));
            }
            #pragma unroll
            for (int mi = 0; mi < 2; mi++)
                #pragma unroll
                for (int nj = 0; nj < 8; nj++) {
                    uint32_t b0 = bf[nj >> 1][(nj & 1) * 2 + 0];
                    uint32_t b1 = bf[nj >> 1][(nj & 1) * 2 + 1];
                    asm volatile(
                        "mma.sync.aligned.m16n8k16.row.col.f32.f16.f16.f32 "
                        "{%0,%1,%2,%3}, {%4,%5,%6,%7}, {%8,%9}, {%0,%1,%2,%3};"
                        : "+f"(acc[mi][nj][0]), "+f"(acc[mi][nj][1]),
                          "+f"(acc[mi][nj][2]), "+f"(acc[mi][nj][3])
                        : "r"(af[mi][0]), "r"(af[mi][1]), "r"(af[mi][2]), "r"(af[mi][3]),
                          "r"(b0), "r"(b1));
                }
        }
        __syncthreads();
    }

    // epilogue
    const int g = lane >> 2, tg = lane & 3;
    #pragma unroll
    for (int mi = 0; mi < 2; mi++) {
        int row0 = blk_m + warp_m * 32 + mi * 16 + g;
        #pragma unroll
        for (int nj = 0; nj < 8; nj++) {
            int col = blk_n + warp_n * 64 + nj * 8 + tg * 2;
            if (col >= j.N) continue;
            float b0 = __ldg(j.bias + col), b1 = __ldg(j.bias + col + 1);
            if (j.out_half) {
                __half* C = (__half*)j.C;
                int h = col >> 5, ch = col & 31;
                #pragma unroll
                for (int rr = 0; rr < 2; rr++) {
                    int row = row0 + rr * 8;
                    if (row >= M) continue;
                    __half2 o = __floats2half2_rn(acc[mi][nj][rr * 2 + 0] + b0,
                                                  acc[mi][nj][rr * 2 + 1] + b1);
                    size_t eA = ((size_t)h * VROWS + row) * HD + ch;
                    *(__half2*)(C + eA) = o;
                    int slotB = (row == 0) ? (SEQ + 2) : (row - 1);
                    *(__half2*)(C + COPY_ELEMS + ((size_t)h * VROWS + slotB) * HD + ch) = o;
                }
            } else {
                float* C = (float*)j.C;
                if (row0 < M) {
                    float2 o = make_float2(acc[mi][nj][0] + b0, acc[mi][nj][1] + b1);
                    *(float2*)(C + (size_t)row0 * j.N + col) = o;
                }
                if (row0 + 8 < M) {
                    float2 o = make_float2(acc[mi][nj][2] + b0, acc[mi][nj][3] + b1);
                    *(float2*)(C + (size_t)(row0 + 8) * j.N + col) = o;
                }
            }
        }
    }
}

// ---------------- sampling: 8 queries/block, warp=query, pair-aligned gather ----------------
// Packed tap record: int4 { byte_offset, w0_bits, w1_bits, 0 } -> one LDS.128 per tap.
__global__ __launch_bounds__(256) void sample_kernel(
    const __half* __restrict__ value,      // g_val2
    const float* __restrict__ raw,         // [SEQ, 288]
    const float* __restrict__ refp,        // [SEQ, 3, 2]
    __half* __restrict__ outh,             // [SEQ, 256] fp16
    float* __restrict__ attn_out)          // [SEQ, 8, 12] or null
{
    const int q0  = blockIdx.x * 8;
    const int tid = threadIdx.x;

    __shared__ float s_attn[64][LP];            // [q*8+h][p]
    __shared__ __align__(16) int4 s_pk[8][24][NHEADS];  // {bo, w0, w1, 0}

    // ---- stage 1: softmax ----
    if (tid < 64) {
        int q = tid >> 3, h = tid & 7;
        const float* lg = raw + (size_t)(q0 + q) * N2 + NOFF + h * LP;
        float l[LP]; float m = -INFINITY;
        #pragma unroll
        for (int p = 0; p < LP; p++) { l[p] = lg[p]; m = fmaxf(m, l[p]); }
        float s = 0.f;
        #pragma unroll
        for (int p = 0; p < LP; p++) { l[p] = expf(l[p] - m); s += l[p]; }
        float inv = 1.f / s;
        #pragma unroll
        for (int p = 0; p < LP; p++) s_attn[q * 8 + h][p] = l[p] * inv;
    }
    __syncthreads();

    // ---- stage 2: tap setup (768 slots, 3 per thread) ----
    #pragma unroll
    for (int i = 0; i < 3; i++) {
        int s = i * 256 + tid;
        int q = s / 96; int rem = s - q * 96;
        int h = rem / LP; int p = rem - h * LP;

        float a = s_attn[q * 8 + h][p];
        if (attn_out) attn_out[((size_t)(q0 + q) * NHEADS + h) * LP + p] = a;

        const float* rq = raw + (size_t)(q0 + q) * N2;
        float2 off = *(const float2*)(rq + (h * LP + p) * 2);
        int lvl = p >> 2;
        int Wi = 160 >> lvl;
        int start = (lvl == 0) ? 0 : ((lvl == 1) ? 25600 : 32000);
        float dim = (float)Wi;
        float2 rp = *(const float2*)(refp + ((size_t)(q0 + q) * NLEVELS + lvl) * 2);

        float px = (rp.x + off.x / dim) * dim - 0.5f;
        float py = (rp.y + off.y / dim) * dim - 0.5f;

        float x0f = floorf(px), y0f = floorf(py);
        int x0 = (int)x0f, y0 = (int)y0f;
        float wx1 = px - x0f, wy1 = py - y0f;
        float wx0 = 1.f - wx1, wy0 = 1.f - wy1;

        bool xok0 = (x0 >= 0)  && (x0 < Wi);
        bool xok1 = (x0 >= -1) && (x0 + 1 < Wi);

        const int hbase = h * VROWS;
        #pragma unroll
        for (int ytap = 0; ytap < 2; ytap++) {
            int y = y0 + ytap;
            bool yok = (y >= 0) && (y < Wi);
            float wy = ytap ? wy1 : wy0;
            float w0 = (yok && xok0) ? a * wy * wx0 : 0.f;
            float w1 = (yok && xok1) ? a * wy * wx1 : 0.f;
            int r = start + y * Wi + x0;
            int base;
            if (!yok) {
                base = 0; w0 = 0.f; w1 = 0.f;
            } else if (r < 0) {
                base = hbase * 64;          // rows (0,1): first half holds r+1 = 0
                w0 = w1; w1 = 0.f;
            } else if (r & 1) {
                base = COPYSZB + (hbase + (r - 1)) * 64;   // copy B, aligned
            } else {
                base = (hbase + r) * 64;                    // copy A, aligned
            }
            s_pk[q][p * 2 + ytap][h] =
                make_int4(base, __float_as_int(w0), __float_as_int(w1), 0);
        }
    }
    __syncthreads();

    // ---- stage 3: gather ----
    {
        const int wq   = tid >> 5;          // query within block
        const int lane = tid & 31;
        const int h0   = lane >> 3;         // head low bits (0-3)
        const int xh   = (lane >> 2) & 1;   // which 64B half (x-tap)
        const int b16  = lane & 7;          // 16B chunk within 128B
        const char* vbase = (const char*)value + b16 * 16;   // fold per-lane chunk

        unsigned long long acc[2][4];
        #pragma unroll
        for (int gidx = 0; gidx < 2; gidx++)
            #pragma unroll
            for (int k = 0; k < 4; k++) acc[gidx][k] = 0;

        for (int pt = 0; pt < LP; pt++) {
            #pragma unroll
            for (int jj = 0; jj < 4; jj++) {
                const int ytap = jj >> 1, hgrp = jj & 1;
                const int head = hgrp * 4 + h0;
                const int idx = pt * 2 + ytap;
                int4 R = s_pk[wq][idx][head];           // one LDS.128
                float w = __int_as_float(xh ? R.z : R.y);
                uint4 v = __ldg((const uint4*)(vbase + R.x));
                unsigned long long wp2 = pack_f32x2(w, w);
                float2 f0 = __half22float2(*reinterpret_cast<__half2*>(&v.x));
                float2 f1 = __half22float2(*reinterpret_cast<__half2*>(&v.y));
                float2 f2 = __half22float2(*reinterpret_cast<__half2*>(&v.z));
                float2 f3 = __half22float2(*reinterpret_cast<__half2*>(&v.w));
                fma_f32x2(acc[hgrp][0], pack_f32x2(f0.x, f0.y), wp2);
                fma_f32x2(acc[hgrp][1], pack_f32x2(f1.x, f1.y), wp2);
                fma_f32x2(acc[hgrp][2], pack_f32x2(f2.x, f2.y), wp2);
                fma_f32x2(acc[hgrp][3], pack_f32x2(f3.x, f3.y), wp2);
            }
        }

        // combine x-halves (partner lane = lane ^ 4)
        #pragma unroll
        for (int gidx = 0; gidx < 2; gidx++)
            #pragma unroll
            for (int k = 0; k < 4; k++) {
                unsigned long long other =
                    __shfl_xor_sync(0xffffffffu, acc[gidx][k], 4);
                acc[gidx][k] = add_f32x2(acc[gidx][k], other);
            }

        if (xh == 0) {
            const int oct = lane & 3;
            #pragma unroll
            for (int gidx = 0; gidx < 2; gidx++) {
                const int head = gidx * 4 + h0;
                float f[8];
                unpack_f32x2(acc[gidx][0], f[0], f[1]);
                unpack_f32x2(acc[gidx][1], f[2], f[3]);
                unpack_f32x2(acc[gidx][2], f[4], f[5]);
                unpack_f32x2(acc[gidx][3], f[6], f[7]);
                uint4 O = cvt8_f16(make_float4(f[0], f[1], f[2], f[3]),
                                   make_float4(f[4], f[5], f[6], f[7]));
                size_t orow = (size_t)(q0 + wq) * DMODEL + head * HD + oct * 8;
                *(uint4*)(outh + orow) = O;
            }
        }
    }
}

// ---------------- launch ----------------
extern "C" void kernel_launch(void* const* d_in, const int* in_sizes, int n_in,
                              void* d_out, int out_size)
{
    const float* hidden = (const float*)d_in[0];
    const float* enc    = (const float*)d_in[1];
    const float* pos    = (const float*)d_in[2];
    const float* refp   = (const float*)d_in[3];
    const float* Wv     = (const float*)d_in[4];
    const float* bv     = (const float*)d_in[5];
    const float* Ws     = (const float*)d_in[6];
    const float* bs     = (const float*)d_in[7];
    const float* Wa     = (const float*)d_in[8];
    const float* ba     = (const float*)d_in[9];
    const float* Wo     = (const float*)d_in[10];
    const float* bo     = (const float*)d_in[11];

    float* out = (float*)d_out;
    float* attn_ptr = ((size_t)out_size >= OUT_ELEMS + ATTN_ELEMS) ? (out + OUT_ELEMS) : nullptr;

    __half *p_val2, *p_ench, *p_hsh, *p_samph, *p_wvh, *p_w2h, *p_woh;
    float *p_raw, *p_b2;
    cudaGetSymbolAddress((void**)&p_val2,  g_val2);
    cudaGetSymbolAddress((void**)&p_raw,   g_raw);
    cudaGetSymbolAddress((void**)&p_b2,    g_b2);
    cudaGetSymbolAddress((void**)&p_ench,  g_ench);
    cudaGetSymbolAddress((void**)&p_hsh,   g_hsh);
    cudaGetSymbolAddress((void**)&p_samph, g_samph);
    cudaGetSymbolAddress((void**)&p_wvh,   g_wvh);
    cudaGetSymbolAddress((void**)&p_w2h,   g_w2h);
    cudaGetSymbolAddress((void**)&p_woh,   g_woh);

    static bool attr_set = false;
    if (!attr_set) {
        cudaFuncSetAttribute(gemm_kernel, cudaFuncAttributeMaxDynamicSharedMemorySize, GEMM_SMEM);
        attr_set = true;
    }

    // 1) merged weight prep + activation conversion (one launch)
    prep_conv_kernel<<<100 + (2 * SEQ * 32 + 255) / 256, 256>>>(
        Wv, Ws, bs, Wa, ba, Wo, enc, hidden, pos);

    const int grid_m = (SEQ + 127) / 128;   // 263

    // 2) fused: value(fp16, head-major dual copy) AND raw projections
    GemmJob jv = { p_ench, p_wvh, bv,   p_val2, DMODEL, 1 };
    GemmJob jr = { p_hsh,  p_w2h, p_b2, p_raw,  N2,     0 };
    {
        dim3 g(5, grid_m);
        gemm_kernel<<<g, 256, GEMM_SMEM>>>(jv, jr, 2, SEQ);
    }

    // 3) softmax + deformable sampling (emits fp16), 8 queries per block
    sample_kernel<<<SEQ / 8, 256>>>(p_val2, p_raw, refp, p_samph, attn_ptr);

    // 4) output = samp @ Wo^T + bo
    GemmJob jo = { p_samph, p_woh, bo, out, DMODEL, 0 };
    {
        dim3 g(2, grid_m);
        gemm_kernel<<<g, 256, GEMM_SMEM>>>(jo, jo, 2, SEQ);
    }
}

// round 16
// speedup vs baseline: 1.0298x; 1.0298x over previous
#include <cuda_runtime.h>
#include <cuda_bf16.h>
#include <cuda_fp16.h>
#include <math.h>
#include <stddef.h>
#include <stdint.h>

// ---------------- problem constants ----------------
#define SEQ      33600
#define DMODEL   256
#define NHEADS   8
#define NLEVELS  3
#define NPOINTS  4
#define LP       (NLEVELS * NPOINTS)        // 12
#define HD       (DMODEL / NHEADS)          // 32
#define NOFF     (NHEADS * LP * 2)          // 192
#define NATT     (NHEADS * LP)              // 96
#define N2       (NOFF + NATT)              // 288
#define KHL      512                         // weight hi|lo width
#define VROWS    (SEQ + 4)                   // padded rows per head
#define COPY_ELEMS ((size_t)NHEADS * VROWS * HD)
#define COPYSZB  ((int)(COPY_ELEMS * 2))
#define OUT_ELEMS  ((size_t)SEQ * DMODEL)
#define ATTN_ELEMS ((size_t)SEQ * NHEADS * LP)

#define GEMM_SMEM  (3 * 32768)               // 3 stages x (16KB A + 16KB B)

// ---------------- scratch (device globals) ----------------
__device__ __half g_val2[2 * COPY_ELEMS];     // value, head-major, copies A|B(shifted)
__device__ float  g_raw [SEQ * N2];
__device__ float  g_b2  [N2];
__device__ __half g_ench [SEQ * DMODEL];      // enc        fp16
__device__ __half g_hsh  [SEQ * DMODEL];      // hidden+pos fp16
__device__ __half g_samph[SEQ * DMODEL];      // sampled    fp16
__device__ __half g_wvh[DMODEL * KHL];        // weights fp16 hi|lo
__device__ __half g_w2h[N2 * KHL];
__device__ __half g_woh[DMODEL * KHL];

// ---------------- helpers ----------------
__device__ __forceinline__ uint32_t pack_h2(__half a, __half b) {
    __half2 t = __halves2half2(a, b);
    return *reinterpret_cast<uint32_t*>(&t);
}
__device__ __forceinline__ void split_f16(float x, __half& h, __half& l) {
    h = __float2half_rn(x);
    l = __float2half_rn(x - __half2float(h));
}
__device__ __forceinline__ void cvt8_hilo(float4 a, float4 b, uint4& H, uint4& L) {
    __half h[8], l[8];
    split_f16(a.x, h[0], l[0]); split_f16(a.y, h[1], l[1]);
    split_f16(a.z, h[2], l[2]); split_f16(a.w, h[3], l[3]);
    split_f16(b.x, h[4], l[4]); split_f16(b.y, h[5], l[5]);
    split_f16(b.z, h[6], l[6]); split_f16(b.w, h[7], l[7]);
    H = make_uint4(pack_h2(h[0],h[1]), pack_h2(h[2],h[3]), pack_h2(h[4],h[5]), pack_h2(h[6],h[7]));
    L = make_uint4(pack_h2(l[0],l[1]), pack_h2(l[2],l[3]), pack_h2(l[4],l[5]), pack_h2(l[6],l[7]));
}
__device__ __forceinline__ uint4 cvt8_f16(float4 a, float4 b) {
    __half2 p0 = __floats2half2_rn(a.x, a.y);
    __half2 p1 = __floats2half2_rn(a.z, a.w);
    __half2 p2 = __floats2half2_rn(b.x, b.y);
    __half2 p3 = __floats2half2_rn(b.z, b.w);
    return make_uint4(*(uint32_t*)&p0, *(uint32_t*)&p1, *(uint32_t*)&p2, *(uint32_t*)&p3);
}
__device__ __forceinline__ void cp_async16(uint32_t dst, const void* src, bool pred) {
    int sz = pred ? 16 : 0;
    asm volatile("cp.async.cg.shared.global [%0], [%1], 16, %2;"
                 :: "r"(dst), "l"(src), "r"(sz) : "memory");
}
// packed f32x2 helpers (sm_100+ base feature)
__device__ __forceinline__ unsigned long long pack_f32x2(float lo, float hi) {
    unsigned long long r;
    asm("mov.b64 %0, {%1, %2};" : "=l"(r) : "f"(lo), "f"(hi));
    return r;
}
__device__ __forceinline__ void unpack_f32x2(unsigned long long v, float& lo, float& hi) {
    asm("mov.b64 {%0, %1}, %2;" : "=f"(lo), "=f"(hi) : "l"(v));
}
__device__ __forceinline__ void fma_f32x2(unsigned long long& d,
                                          unsigned long long a, unsigned long long b) {
    asm("fma.rn.f32x2 %0, %1, %2, %0;" : "+l"(d) : "l"(a), "l"(b));
}
__device__ __forceinline__ unsigned long long add_f32x2(unsigned long long a, unsigned long long b) {
    unsigned long long r;
    asm("add.rn.f32x2 %0, %1, %2;" : "=l"(r) : "l"(a), "l"(b));
    return r;
}

// ---------------- merged prep + activation conversion ----------------
__global__ __launch_bounds__(256) void prep_conv_kernel(
    const float* __restrict__ Wv, const float* __restrict__ Ws, const float* __restrict__ bs,
    const float* __restrict__ Wa, const float* __restrict__ ba, const float* __restrict__ Wo,
    const float* __restrict__ enc, const float* __restrict__ hidden, const float* __restrict__ pos)
{
    if (blockIdx.x < 100) {
        int u = blockIdx.x * 256 + threadIdx.x;     // one unit = 8 floats
        const int TOTAL_ROWS = DMODEL + N2 + DMODEL;  // 800
        if (u < TOTAL_ROWS * 32) {
            int row = u >> 5, uc = u & 31;
            const float* src;
            __half* dst;
            if (row < DMODEL) { src = Wv + (size_t)row * DMODEL; dst = g_wvh + (size_t)row * KHL; }
            else if (row < DMODEL + N2) {
                int n = row - DMODEL;
                src = (n < NOFF) ? (Ws + (size_t)n * DMODEL) : (Wa + (size_t)(n - NOFF) * DMODEL);
                dst = g_w2h + (size_t)n * KHL;
            } else {
                int n = row - DMODEL - N2;
                src = Wo + (size_t)n * DMODEL; dst = g_woh + (size_t)n * KHL;
            }
            float4 a = *(const float4*)(src + uc * 8);
            float4 b = *(const float4*)(src + uc * 8 + 4);
            uint4 H, L; cvt8_hilo(a, b, H, L);
            *(uint4*)(dst + uc * 8)          = H;
            *(uint4*)(dst + DMODEL + uc * 8) = L;
        }
        if (u < N2) g_b2[u] = (u < NOFF) ? bs[u] : ba[u - NOFF];
    } else {
        int u = (blockIdx.x - 100) * 256 + threadIdx.x;
        const int PER = SEQ * 32;                 // units per tensor (8 floats each)
        if (u >= 2 * PER) return;
        bool second = (u >= PER);
        int v = second ? (u - PER) : u;
        int row = v >> 5, uc = v & 31;
        const float* src = (second ? hidden : enc) + (size_t)row * DMODEL + uc * 8;
        float4 a = *(const float4*)(src);
        float4 b = *(const float4*)(src + 4);
        if (second) {
            const float* p2 = pos + (size_t)row * DMODEL + uc * 8;
            float4 u0 = *(const float4*)p2, u1 = *(const float4*)(p2 + 4);
            a.x += u0.x; a.y += u0.y; a.z += u0.z; a.w += u0.w;
            b.x += u1.x; b.y += u1.y; b.z += u1.z; b.w += u1.w;
        }
        __half* dst = (second ? g_hsh : g_ench) + (size_t)row * DMODEL;
        *(uint4*)(dst + uc * 8) = cvt8_f16(a, b);
    }
}

// ---------------- GEMM: C[M,N] = A @ Bw^T + bias (fp16 A, fp16 hi/lo B, 2 passes) ----------------
struct GemmJob {
    const __half* A;
    const __half* Bw;
    const float* bias;
    void* C;
    int N;
    int out_half;   // 1: write __half head-major dual-copy (value), 0: write float
};

__global__ __launch_bounds__(256, 2) void gemm_kernel(GemmJob j0, GemmJob j1, int xsplit, int M)
{
    extern __shared__ char smem[];   // 3 stages x (16KB A + 16KB B)

    const bool first = ((int)blockIdx.x < xsplit);
    GemmJob j = first ? j0 : j1;
    const int nb = first ? blockIdx.x : (blockIdx.x - xsplit);
    const int blk_m = blockIdx.y * 128, blk_n = nb * 128;

    const int tid = threadIdx.x;
    const int wid = tid >> 5, lane = tid & 31;
    const int warp_m = wid & 3, warp_n = wid >> 2;
    const int t4 = lane >> 3, r8 = lane & 7;

    const uint32_t s_base = (uint32_t)__cvta_generic_to_shared(smem);

    int lrow[4], luc[4];
    uint32_t s_off[4];
    bool predA[4], predB[4];
    const __half* srcA[4];
    const __half* srcB[4];
    #pragma unroll
    for (int i = 0; i < 4; i++) {
        int u = tid + 256 * i;
        lrow[i] = u >> 3; luc[i] = u & 7;
        s_off[i] = (uint32_t)(lrow[i] * 128 + ((luc[i] ^ (lrow[i] & 7)) << 4));
        int gm = blk_m + lrow[i];
        predA[i] = gm < M;
        srcA[i] = j.A + (size_t)(predA[i] ? gm : 0) * DMODEL + luc[i] * 8;
        int gn = blk_n + lrow[i];
        predB[i] = gn < j.N;
        srcB[i] = j.Bw + (size_t)(predB[i] ? gn : 0) * KHL + luc[i] * 8;
    }

    float acc[2][8][4];
    #pragma unroll
    for (int a = 0; a < 2; a++)
        #pragma unroll
        for (int b = 0; b < 8; b++)
            #pragma unroll
            for (int c = 0; c < 4; c++) acc[a][b][c] = 0.f;

    auto issue = [&](int c, int buf) {
        int pass = c >> 2, kk = (c & 3) * 64;
        int bcol = pass * DMODEL + kk;
        uint32_t abase = s_base + buf * 32768;
        uint32_t bbase = abase + 16384;
        #pragma unroll
        for (int i = 0; i < 4; i++) {
            cp_async16(abase + s_off[i], srcA[i] + kk,   predA[i]);
            cp_async16(bbase + s_off[i], srcB[i] + bcol, predB[i]);
        }
        asm volatile("cp.async.commit_group;" ::: "memory");
    };

    issue(0, 0);
    issue(1, 1);

    for (int c = 0; c < 8; c++) {
        if (c + 2 < 8) {
            issue(c + 2, (c + 2) % 3);
            asm volatile("cp.async.wait_group 2;" ::: "memory");
        } else if (c == 6) {
            asm volatile("cp.async.wait_group 1;" ::: "memory");
        } else {
            asm volatile("cp.async.wait_group 0;" ::: "memory");
        }
        __syncthreads();

        const uint32_t abase = s_base + (c % 3) * 32768;
        const uint32_t bbase = abase + 16384;

        #pragma unroll
        for (int ks = 0; ks < 4; ks++) {
            uint32_t af[2][4];
            #pragma unroll
            for (int mi = 0; mi < 2; mi++) {
                int row = warp_m * 32 + mi * 16 + (t4 & 1) * 8 + r8;
                int kch = ks * 2 + (t4 >> 1);
                uint32_t addr = abase + (uint32_t)(row * 128 + ((kch ^ (row & 7)) << 4));
                asm volatile("ldmatrix.sync.aligned.m8n8.x4.shared.b16 {%0,%1,%2,%3}, [%4];"
                             : "=r"(af[mi][0]), "=r"(af[mi][1]), "=r"(af[mi][2]), "=r"(af[mi][3])
                             : "r"(addr));
            }
            uint32_t bf[4][4];
            #pragma unroll
            for (int jj = 0; jj < 4; jj++) {
                int nrow = warp_n * 64 + jj * 16 + (t4 >> 1) * 8 + r8;
                int kch = ks * 2 + (t4 & 1);
                uint32_t addr = bbase + (uint32_t)(nrow * 128 + ((kch ^ (nrow & 7)) << 4));
                asm volatile("ldmatrix.sync.aligned.m8n8.x4.shared.b16 {%0,%1,%2,%3}, [%4];"
                             : "=r"(bf[jj][0]), "=r"(bf[jj][1]), "=r"(bf[jj][2]), "=r"(bf[jj][3])
                             : "r"(addr));
            }
            #pragma unroll
            for (int mi = 0; mi < 2; mi++)
                #pragma unroll
                for (int nj = 0; nj < 8; nj++) {
                    uint32_t b0 = bf[nj >> 1][(nj & 1) * 2 + 0];
                    uint32_t b1 = bf[nj >> 1][(nj & 1) * 2 + 1];
                    asm volatile(
                        "mma.sync.aligned.m16n8k16.row.col.f32.f16.f16.f32 "
                        "{%0,%1,%2,%3}, {%4,%5,%6,%7}, {%8,%9}, {%0,%1,%2,%3};"
                        : "+f"(acc[mi][nj][0]), "+f"(acc[mi][nj][1]),
                          "+f"(acc[mi][nj][2]), "+f"(acc[mi][nj][3])
                        : "r"(af[mi][0]), "r"(af[mi][1]), "r"(af[mi][2]), "r"(af[mi][3]),
                          "r"(b0), "r"(b1));
                }
        }
        __syncthreads();
    }

    // epilogue
    const int g = lane >> 2, tg = lane & 3;
    #pragma unroll
    for (int mi = 0; mi < 2; mi++) {
        int row0 = blk_m + warp_m * 32 + mi * 16 + g;
        #pragma unroll
        for (int nj = 0; nj < 8; nj++) {
            int col = blk_n + warp_n * 64 + nj * 8 + tg * 2;
            if (col >= j.N) continue;
            float b0 = __ldg(j.bias + col), b1 = __ldg(j.bias + col + 1);
            if (j.out_half) {
                __half* C = (__half*)j.C;
                int h = col >> 5, ch = col & 31;
                #pragma unroll
                for (int rr = 0; rr < 2; rr++) {
                    int row = row0 + rr * 8;
                    if (row >= M) continue;
                    __half2 o = __floats2half2_rn(acc[mi][nj][rr * 2 + 0] + b0,
                                                  acc[mi][nj][rr * 2 + 1] + b1);
                    size_t eA = ((size_t)h * VROWS + row) * HD + ch;
                    *(__half2*)(C + eA) = o;
                    int slotB = (row == 0) ? (SEQ + 2) : (row - 1);
                    *(__half2*)(C + COPY_ELEMS + ((size_t)h * VROWS + slotB) * HD + ch) = o;
                }
            } else {
                float* C = (float*)j.C;
                if (row0 < M) {
                    float2 o = make_float2(acc[mi][nj][0] + b0, acc[mi][nj][1] + b1);
                    *(float2*)(C + (size_t)row0 * j.N + col) = o;
                }
                if (row0 + 8 < M) {
                    float2 o = make_float2(acc[mi][nj][2] + b0, acc[mi][nj][3] + b1);
                    *(float2*)(C + (size_t)(row0 + 8) * j.N + col) = o;
                }
            }
        }
    }
}

// ---------------- sampling: 8 queries/block, warp=query, pair-aligned gather ----------------
__global__ __launch_bounds__(256) void sample_kernel(
    const __half* __restrict__ value,      // g_val2
    const float* __restrict__ raw,         // [SEQ, 288]
    const float* __restrict__ refp,        // [SEQ, 3, 2]
    __half* __restrict__ outh,             // [SEQ, 256] fp16
    float* __restrict__ attn_out)          // [SEQ, 8, 12] or null
{
    const int q0  = blockIdx.x * 8;
    const int tid = threadIdx.x;

    __shared__ float s_attn[64][LP];            // [q*8+h][p]
    __shared__ int   s_bo[8][24][NHEADS];       // [q][p*2+ytap][h] byte offset
    __shared__ float s_w [8][24][NHEADS][2];    // weights for the two 64B halves

    // ---- stage 1: softmax ----
    if (tid < 64) {
        int q = tid >> 3, h = tid & 7;
        const float* lg = raw + (size_t)(q0 + q) * N2 + NOFF + h * LP;
        float l[LP]; float m = -INFINITY;
        #pragma unroll
        for (int p = 0; p < LP; p++) { l[p] = lg[p]; m = fmaxf(m, l[p]); }
        float s = 0.f;
        #pragma unroll
        for (int p = 0; p < LP; p++) { l[p] = expf(l[p] - m); s += l[p]; }
        float inv = 1.f / s;
        #pragma unroll
        for (int p = 0; p < LP; p++) s_attn[q * 8 + h][p] = l[p] * inv;
    }
    __syncthreads();

    // ---- stage 2: tap setup (768 slots, 3 per thread) ----
    #pragma unroll
    for (int i = 0; i < 3; i++) {
        int s = i * 256 + tid;
        int q = s / 96; int rem = s - q * 96;
        int h = rem / LP; int p = rem - h * LP;

        float a = s_attn[q * 8 + h][p];
        if (attn_out) attn_out[((size_t)(q0 + q) * NHEADS + h) * LP + p] = a;

        const float* rq = raw + (size_t)(q0 + q) * N2;
        float2 off = *(const float2*)(rq + (h * LP + p) * 2);
        int lvl = p >> 2;
        int Wi = 160 >> lvl;
        int start = (lvl == 0) ? 0 : ((lvl == 1) ? 25600 : 32000);
        float dim = (float)Wi;
        float2 rp = *(const float2*)(refp + ((size_t)(q0 + q) * NLEVELS + lvl) * 2);

        float px = (rp.x + off.x / dim) * dim - 0.5f;
        float py = (rp.y + off.y / dim) * dim - 0.5f;

        float x0f = floorf(px), y0f = floorf(py);
        int x0 = (int)x0f, y0 = (int)y0f;
        float wx1 = px - x0f, wy1 = py - y0f;
        float wx0 = 1.f - wx1, wy0 = 1.f - wy1;

        bool xok0 = (x0 >= 0)  && (x0 < Wi);
        bool xok1 = (x0 >= -1) && (x0 + 1 < Wi);

        const int hbase = h * VROWS;
        #pragma unroll
        for (int ytap = 0; ytap < 2; ytap++) {
            int y = y0 + ytap;
            bool yok = (y >= 0) && (y < Wi);
            float wy = ytap ? wy1 : wy0;
            float w0 = (yok && xok0) ? a * wy * wx0 : 0.f;
            float w1 = (yok && xok1) ? a * wy * wx1 : 0.f;
            int r = start + y * Wi + x0;
            int base;
            if (!yok) {
                base = 0; w0 = 0.f; w1 = 0.f;
            } else if (r < 0) {
                base = hbase * 64;          // rows (0,1): first half holds r+1 = 0
                w0 = w1; w1 = 0.f;
            } else if (r & 1) {
                base = COPYSZB + (hbase + (r - 1)) * 64;   // copy B, aligned
            } else {
                base = (hbase + r) * 64;                    // copy A, aligned
            }
            s_bo[q][p * 2 + ytap][h] = base;
            s_w[q][p * 2 + ytap][h][0] = w0;
            s_w[q][p * 2 + ytap][h][1] = w1;
        }
    }
    __syncthreads();

    // ---- stage 3: gather (point loop unrolled x2 for MLP) ----
    {
        const int wq   = tid >> 5;          // query within block
        const int lane = tid & 31;
        const int h0   = lane >> 3;         // head low bits (0-3)
        const int xh   = (lane >> 2) & 1;   // which 64B half (x-tap)
        const int b16  = lane & 7;          // 16B chunk within 128B
        const char* vbytes = (const char*)value + b16 * 16;

        unsigned long long acc[2][4];
        #pragma unroll
        for (int gidx = 0; gidx < 2; gidx++)
            #pragma unroll
            for (int k = 0; k < 4; k++) acc[gidx][k] = 0;

        #pragma unroll 2
        for (int pt = 0; pt < LP; pt++) {
            #pragma unroll
            for (int jj = 0; jj < 4; jj++) {
                const int ytap = jj >> 1, hgrp = jj & 1;
                const int head = hgrp * 4 + h0;
                const int idx = pt * 2 + ytap;
                int   bo = s_bo[wq][idx][head];
                float w  = s_w [wq][idx][head][xh];
                uint4 v = __ldg((const uint4*)(vbytes + bo));
                unsigned long long wp2 = pack_f32x2(w, w);
                float2 f0 = __half22float2(*reinterpret_cast<__half2*>(&v.x));
                float2 f1 = __half22float2(*reinterpret_cast<__half2*>(&v.y));
                float2 f2 = __half22float2(*reinterpret_cast<__half2*>(&v.z));
                float2 f3 = __half22float2(*reinterpret_cast<__half2*>(&v.w));
                fma_f32x2(acc[hgrp][0], pack_f32x2(f0.x, f0.y), wp2);
                fma_f32x2(acc[hgrp][1], pack_f32x2(f1.x, f1.y), wp2);
                fma_f32x2(acc[hgrp][2], pack_f32x2(f2.x, f2.y), wp2);
                fma_f32x2(acc[hgrp][3], pack_f32x2(f3.x, f3.y), wp2);
            }
        }

        // combine x-halves (partner lane = lane ^ 4)
        #pragma unroll
        for (int gidx = 0; gidx < 2; gidx++)
            #pragma unroll
            for (int k = 0; k < 4; k++) {
                unsigned long long other =
                    __shfl_xor_sync(0xffffffffu, acc[gidx][k], 4);
                acc[gidx][k] = add_f32x2(acc[gidx][k], other);
            }

        if (xh == 0) {
            const int oct = lane & 3;
            #pragma unroll
            for (int gidx = 0; gidx < 2; gidx++) {
                const int head = gidx * 4 + h0;
                float f[8];
                unpack_f32x2(acc[gidx][0], f[0], f[1]);
                unpack_f32x2(acc[gidx][1], f[2], f[3]);
                unpack_f32x2(acc[gidx][2], f[4], f[5]);
                unpack_f32x2(acc[gidx][3], f[6], f[7]);
                uint4 O = cvt8_f16(make_float4(f[0], f[1], f[2], f[3]),
                                   make_float4(f[4], f[5], f[6], f[7]));
                size_t orow = (size_t)(q0 + wq) * DMODEL + head * HD + oct * 8;
                *(uint4*)(outh + orow) = O;
            }
        }
    }
}

// ---------------- launch ----------------
extern "C" void kernel_launch(void* const* d_in, const int* in_sizes, int n_in,
                              void* d_out, int out_size)
{
    const float* hidden = (const float*)d_in[0];
    const float* enc    = (const float*)d_in[1];
    const float* pos    = (const float*)d_in[2];
    const float* refp   = (const float*)d_in[3];
    const float* Wv     = (const float*)d_in[4];
    const float* bv     = (const float*)d_in[5];
    const float* Ws     = (const float*)d_in[6];
    const float* bs     = (const float*)d_in[7];
    const float* Wa     = (const float*)d_in[8];
    const float* ba     = (const float*)d_in[9];
    const float* Wo     = (const float*)d_in[10];
    const float* bo     = (const float*)d_in[11];

    float* out = (float*)d_out;
    float* attn_ptr = ((size_t)out_size >= OUT_ELEMS + ATTN_ELEMS) ? (out + OUT_ELEMS) : nullptr;

    __half *p_val2, *p_ench, *p_hsh, *p_samph, *p_wvh, *p_w2h, *p_woh;
    float *p_raw, *p_b2;
    cudaGetSymbolAddress((void**)&p_val2,  g_val2);
    cudaGetSymbolAddress((void**)&p_raw,   g_raw);
    cudaGetSymbolAddress((void**)&p_b2,    g_b2);
    cudaGetSymbolAddress((void**)&p_ench,  g_ench);
    cudaGetSymbolAddress((void**)&p_hsh,   g_hsh);
    cudaGetSymbolAddress((void**)&p_samph, g_samph);
    cudaGetSymbolAddress((void**)&p_wvh,   g_wvh);
    cudaGetSymbolAddress((void**)&p_w2h,   g_w2h);
    cudaGetSymbolAddress((void**)&p_woh,   g_woh);

    static bool attr_set = false;
    if (!attr_set) {
        cudaFuncSetAttribute(gemm_kernel, cudaFuncAttributeMaxDynamicSharedMemorySize, GEMM_SMEM);
        attr_set = true;
    }

    // 1) merged weight prep + activation conversion (one launch)
    prep_conv_kernel<<<100 + (2 * SEQ * 32 + 255) / 256, 256>>>(
        Wv, Ws, bs, Wa, ba, Wo, enc, hidden, pos);

    const int grid_m = (SEQ + 127) / 128;   // 263

    // 2) fused: value(fp16, head-major dual copy) AND raw projections
    GemmJob jv = { p_ench, p_wvh, bv,   p_val2, DMODEL, 1 };
    GemmJob jr = { p_hsh,  p_w2h, p_b2, p_raw,  N2,     0 };
    {
        dim3 g(5, grid_m);
        gemm_kernel<<<g, 256, GEMM_SMEM>>>(jv, jr, 2, SEQ);
    }

    // 3) softmax + deformable sampling (emits fp16), 8 queries per block
    sample_kernel<<<SEQ / 8, 256>>>(p_val2, p_raw, refp, p_samph, attn_ptr);

    // 4) output = samp @ Wo^T + bo
    GemmJob jo = { p_samph, p_woh, bo, out, DMODEL, 0 };
    {
        dim3 g(2, grid_m);
        gemm_kernel<<<g, 256, GEMM_SMEM>>>(jo, jo, 2, SEQ);
    }
}